// round 1
// baseline (speedup 1.0000x reference)
#include <cuda_runtime.h>
#include <cuda_bf16.h>
#include <stdint.h>

// HashEmbedder (instant-NGP style multiresolution hash grid)
// x:      [N,3] float32  (d_in[0])
// tables: [16, 2^19, 2] float32  (d_in[1])
// out:    [N, 32] float32 (level-major per point)

#define NL 16
#define LOG2_T 19
#define TSIZE (1u << LOG2_T)
#define TMASK (TSIZE - 1u)
#define P1 2654435761u
#define P2 805459861u

#define TPB 128           // threads per block (points per block)
#define SROW 33           // padded smem row (33 floats) -> conflict-free

// floor(16 * 2^(l/3)) — exact-integer levels (3,6,9,12,15) taken on the
// "true value" side; revisit if rel_err indicates the reference rounded down.
__device__ __constant__ float c_res[NL] = {
    16.f, 20.f, 25.f, 32.f, 40.f, 50.f, 64.f, 80.f,
    101.f, 128.f, 161.f, 203.f, 256.f, 322.f, 406.f, 512.f
};

__device__ __forceinline__ float2 lerp2(float2 a, float2 b, float w) {
    float omw = 1.0f - w;
    float2 r;
    r.x = a.x * omw + b.x * w;
    r.y = a.y * omw + b.y * w;
    return r;
}

__global__ __launch_bounds__(TPB)
void hashgrid_kernel(const float* __restrict__ x,
                     const float* __restrict__ tables,
                     float* __restrict__ out,
                     int n)
{
    __shared__ float st[TPB * SROW];

    const int tid = threadIdx.x;
    const int i   = blockIdx.x * TPB + tid;
    const bool valid = (i < n);

    float px = 0.f, py = 0.f, pz = 0.f;
    if (valid) {
        px = x[3 * i + 0];
        py = x[3 * i + 1];
        pz = x[3 * i + 2];
    }
    // clamp for voxel index; weights use the UNclamped coords (matches ref)
    const float cx = fminf(fmaxf(px, -1.0f), 1.0f);
    const float cy = fminf(fmaxf(py, -1.0f), 1.0f);
    const float cz = fminf(fmaxf(pz, -1.0f), 1.0f);

    #pragma unroll
    for (int l = 0; l < NL; ++l) {
        const float res  = c_res[l];
        const float grid = 2.0f / res;

        const float fx = floorf((cx + 1.0f) / grid);
        const float fy = floorf((cy + 1.0f) / grid);
        const float fz = floorf((cz + 1.0f) / grid);

        // vmin = bl*grid + BOX_MIN ; w = (x - vmin)/grid, with unclamped x
        const float wx = (px - (fx * grid + (-1.0f))) / grid;
        const float wy = (py - (fy * grid + (-1.0f))) / grid;
        const float wz = (pz - (fz * grid + (-1.0f))) / grid;

        const uint32_t bx = (uint32_t)(int)fx;
        const uint32_t by = (uint32_t)(int)fy;
        const uint32_t bz = (uint32_t)(int)fz;

        // hash contributions; prime0 == 1
        const uint32_t hx0 = bx;
        const uint32_t hx1 = bx + 1u;
        const uint32_t hy0 = by * P1;
        const uint32_t hy1 = hy0 + P1;
        const uint32_t hz0 = bz * P2;
        const uint32_t hz1 = hz0 + P2;

        const float2* __restrict__ tab =
            reinterpret_cast<const float2*>(tables) + (size_t)l * TSIZE;

        // 8 independent gathers (float2 each) — corner order (i,j,k)
        const float2 e000 = __ldg(&tab[(hx0 ^ hy0 ^ hz0) & TMASK]);
        const float2 e001 = __ldg(&tab[(hx0 ^ hy0 ^ hz1) & TMASK]);
        const float2 e010 = __ldg(&tab[(hx0 ^ hy1 ^ hz0) & TMASK]);
        const float2 e011 = __ldg(&tab[(hx0 ^ hy1 ^ hz1) & TMASK]);
        const float2 e100 = __ldg(&tab[(hx1 ^ hy0 ^ hz0) & TMASK]);
        const float2 e101 = __ldg(&tab[(hx1 ^ hy0 ^ hz1) & TMASK]);
        const float2 e110 = __ldg(&tab[(hx1 ^ hy1 ^ hz0) & TMASK]);
        const float2 e111 = __ldg(&tab[(hx1 ^ hy1 ^ hz1) & TMASK]);

        // trilinear: collapse x, then y, then z (matches reference order)
        const float2 a00 = lerp2(e000, e100, wx);
        const float2 a01 = lerp2(e001, e101, wx);
        const float2 a10 = lerp2(e010, e110, wx);
        const float2 a11 = lerp2(e011, e111, wx);
        const float2 b0  = lerp2(a00, a10, wy);
        const float2 b1  = lerp2(a01, a11, wy);
        const float2 r   = lerp2(b0, b1, wz);

        st[tid * SROW + 2 * l + 0] = r.x;
        st[tid * SROW + 2 * l + 1] = r.y;
    }

    __syncthreads();

    // coalesced write-out: block covers rows [blockIdx.x*TPB, +TPB) of out[N,32]
    const int base_pt = blockIdx.x * TPB;
    float* __restrict__ ob = out + (size_t)base_pt * 32;
    #pragma unroll
    for (int j = 0; j < 32; ++j) {
        const int idx = j * TPB + tid;      // 0 .. TPB*32-1, coalesced
        const int p   = idx >> 5;           // point within block
        const int f   = idx & 31;           // feature
        if (base_pt + p < n)
            ob[idx] = st[p * SROW + f];
    }
}

extern "C" void kernel_launch(void* const* d_in, const int* in_sizes, int n_in,
                              void* d_out, int out_size) {
    const float* x      = (const float*)d_in[0];
    const float* tables = (const float*)d_in[1];
    float* out          = (float*)d_out;

    const int n = in_sizes[0] / 3;
    const int blocks = (n + TPB - 1) / TPB;
    hashgrid_kernel<<<blocks, TPB>>>(x, tables, out, n);
}

// round 2
// speedup vs baseline: 2.1800x; 2.1800x over previous
#include <cuda_runtime.h>
#include <cuda_bf16.h>
#include <stdint.h>

// HashEmbedder (instant-NGP style multiresolution hash grid)
// x:      [N,3] float32  (d_in[0])
// tables: [16, 2^19, 2] float32  (d_in[1])
// out:    [N, 32] float32 (level-major per point)
//
// Layout: one thread per (point, level). 256 threads/block = 16 points x 16 levels.
// Warp = 2 points x 16 levels; each thread writes one float2 -> coalesced stores.

#define NL 16
#define LOG2_T 19
#define TSIZE (1u << LOG2_T)
#define TMASK (TSIZE - 1u)
#define P1 2654435761u
#define P2 805459861u

#define TPB 256
#define PPB (TPB / NL)    // 16 points per block

// floor(16 * 2^(l/3))
__device__ __constant__ float c_res[NL] = {
    16.f, 20.f, 25.f, 32.f, 40.f, 50.f, 64.f, 80.f,
    101.f, 128.f, 161.f, 203.f, 256.f, 322.f, 406.f, 512.f
};

__device__ __forceinline__ float2 lerp2(float2 a, float2 b, float w) {
    float omw = 1.0f - w;
    float2 r;
    r.x = a.x * omw + b.x * w;
    r.y = a.y * omw + b.y * w;
    return r;
}

__global__ __launch_bounds__(TPB)
void hashgrid_kernel(const float* __restrict__ x,
                     const float* __restrict__ tables,
                     float* __restrict__ out,
                     int n)
{
    __shared__ float sc[PPB * 3];   // staged coords for the block's 16 points
    __shared__ float sres[NL];      // per-level resolution (smem broadcast, no LDC divergence)

    const int tid  = threadIdx.x;
    const int base = blockIdx.x * PPB;

    if (tid < NL) sres[tid] = c_res[tid];
    if (tid < PPB * 3) {
        const long gidx = (long)base * 3 + tid;
        sc[tid] = (gidx < (long)n * 3) ? x[gidx] : 0.0f;
    }
    __syncthreads();

    const int pl = tid >> 4;        // local point index  (0..15)
    const int l  = tid & (NL - 1);  // level index        (0..15)
    const int p  = base + pl;
    if (p >= n) return;

    const float px = sc[pl * 3 + 0];
    const float py = sc[pl * 3 + 1];
    const float pz = sc[pl * 3 + 2];

    // clamp for voxel index; weights use the UNclamped coords (matches ref)
    const float cx = fminf(fmaxf(px, -1.0f), 1.0f);
    const float cy = fminf(fmaxf(py, -1.0f), 1.0f);
    const float cz = fminf(fmaxf(pz, -1.0f), 1.0f);

    const float res  = sres[l];
    const float grid = 2.0f / res;

    const float fx = floorf((cx + 1.0f) / grid);
    const float fy = floorf((cy + 1.0f) / grid);
    const float fz = floorf((cz + 1.0f) / grid);

    // vmin = bl*grid + BOX_MIN ; w = (x - vmin)/grid, with unclamped x
    const float wx = (px - (fx * grid + (-1.0f))) / grid;
    const float wy = (py - (fy * grid + (-1.0f))) / grid;
    const float wz = (pz - (fz * grid + (-1.0f))) / grid;

    const uint32_t bx = (uint32_t)(int)fx;
    const uint32_t by = (uint32_t)(int)fy;
    const uint32_t bz = (uint32_t)(int)fz;

    // hash contributions; prime0 == 1
    const uint32_t hx0 = bx;
    const uint32_t hx1 = bx + 1u;
    const uint32_t hy0 = by * P1;
    const uint32_t hy1 = hy0 + P1;
    const uint32_t hz0 = bz * P2;
    const uint32_t hz1 = hz0 + P2;

    const float2* __restrict__ tab =
        reinterpret_cast<const float2*>(tables) + ((size_t)l << LOG2_T);

    // 8 independent gathers, all front-batched -> MLP 8 per thread
    const float2 e000 = __ldg(&tab[(hx0 ^ hy0 ^ hz0) & TMASK]);
    const float2 e001 = __ldg(&tab[(hx0 ^ hy0 ^ hz1) & TMASK]);
    const float2 e010 = __ldg(&tab[(hx0 ^ hy1 ^ hz0) & TMASK]);
    const float2 e011 = __ldg(&tab[(hx0 ^ hy1 ^ hz1) & TMASK]);
    const float2 e100 = __ldg(&tab[(hx1 ^ hy0 ^ hz0) & TMASK]);
    const float2 e101 = __ldg(&tab[(hx1 ^ hy0 ^ hz1) & TMASK]);
    const float2 e110 = __ldg(&tab[(hx1 ^ hy1 ^ hz0) & TMASK]);
    const float2 e111 = __ldg(&tab[(hx1 ^ hy1 ^ hz1) & TMASK]);

    // trilinear: collapse x, then y, then z (matches reference order)
    const float2 a00 = lerp2(e000, e100, wx);
    const float2 a01 = lerp2(e001, e101, wx);
    const float2 a10 = lerp2(e010, e110, wx);
    const float2 a11 = lerp2(e011, e111, wx);
    const float2 b0  = lerp2(a00, a10, wy);
    const float2 b1  = lerp2(a01, a11, wy);
    const float2 r   = lerp2(b0, b1, wz);

    // coalesced: warp covers 2 points x 16 levels -> 256B contiguous
    float2* __restrict__ o = reinterpret_cast<float2*>(out) + ((size_t)p << 4) + l;
    *o = r;
}

extern "C" void kernel_launch(void* const* d_in, const int* in_sizes, int n_in,
                              void* d_out, int out_size) {
    const float* x      = (const float*)d_in[0];
    const float* tables = (const float*)d_in[1];
    float* out          = (float*)d_out;

    const int n = in_sizes[0] / 3;
    const int blocks = (n + PPB - 1) / PPB;
    hashgrid_kernel<<<blocks, TPB>>>(x, tables, out, n);
}

// round 3
// speedup vs baseline: 2.2592x; 1.0363x over previous
#include <cuda_runtime.h>
#include <cuda_bf16.h>
#include <stdint.h>

// HashEmbedder (instant-NGP style multiresolution hash grid)
// x:      [N,3] float32  (d_in[0])
// tables: [16, 2^19, 2] float32  (d_in[1])
// out:    [N, 32] float32 (level-major per point)
//
// One thread per (point, level). Key trick: x-prime == 1, so for even bx the
// two x-corners of a (j,k) pair are adjacent table entries -> one LDG.128.

#define NL 16
#define LOG2_T 19
#define TSIZE (1u << LOG2_T)
#define TMASK (TSIZE - 1u)
#define P1 2654435761u
#define P2 805459861u

#define TPB 256
#define PPB (TPB / NL)    // 16 points per block

// floor(16 * 2^(l/3))
__device__ __constant__ float c_res[NL] = {
    16.f, 20.f, 25.f, 32.f, 40.f, 50.f, 64.f, 80.f,
    101.f, 128.f, 161.f, 203.f, 256.f, 322.f, 406.f, 512.f
};

__device__ __forceinline__ float2 lerp2(float2 a, float2 b, float w) {
    float omw = 1.0f - w;
    float2 r;
    r.x = a.x * omw + b.x * w;
    r.y = a.y * omw + b.y * w;
    return r;
}

__global__ __launch_bounds__(TPB)
void hashgrid_kernel(const float* __restrict__ x,
                     const float* __restrict__ tables,
                     float* __restrict__ out,
                     int n)
{
    __shared__ float sc[PPB * 3];   // staged coords for the block's 16 points
    __shared__ float sres[NL];      // per-level resolution (smem broadcast)

    const int tid  = threadIdx.x;
    const int base = blockIdx.x * PPB;

    if (tid < NL) sres[tid] = c_res[tid];
    if (tid < PPB * 3) {
        const long gidx = (long)base * 3 + tid;
        sc[tid] = (gidx < (long)n * 3) ? x[gidx] : 0.0f;
    }
    __syncthreads();

    const int pl = tid >> 4;        // local point index  (0..15)
    const int l  = tid & (NL - 1);  // level index        (0..15)
    const int p  = base + pl;
    if (p >= n) return;

    const float px = sc[pl * 3 + 0];
    const float py = sc[pl * 3 + 1];
    const float pz = sc[pl * 3 + 2];

    // clamp for voxel index; weights use the UNclamped coords (matches ref)
    const float cx = fminf(fmaxf(px, -1.0f), 1.0f);
    const float cy = fminf(fmaxf(py, -1.0f), 1.0f);
    const float cz = fminf(fmaxf(pz, -1.0f), 1.0f);

    const float res  = sres[l];
    const float grid = 2.0f / res;       // single true division
    const float rinv = res * 0.5f;       // exact 1/grid up to 1 ulp of use

    const float fx = floorf((cx + 1.0f) * rinv);
    const float fy = floorf((cy + 1.0f) * rinv);
    const float fz = floorf((cz + 1.0f) * rinv);

    // vmin = bl*grid + BOX_MIN ; w = (x - vmin)/grid, with unclamped x
    const float wx = (px - (fx * grid + (-1.0f))) * rinv;
    const float wy = (py - (fy * grid + (-1.0f))) * rinv;
    const float wz = (pz - (fz * grid + (-1.0f))) * rinv;

    const uint32_t bx = (uint32_t)(int)fx;
    const uint32_t by = (uint32_t)(int)fy;
    const uint32_t bz = (uint32_t)(int)fz;

    const uint32_t hy0 = by * P1;
    const uint32_t hy1 = hy0 + P1;
    const uint32_t hz0 = bz * P2;
    const uint32_t hz1 = hz0 + P2;

    // 4 (j,k) combos; corner x0 index i0 = (bx ^ hjk) & TMASK
    uint32_t hjk0 = hy0 ^ hz0;
    uint32_t hjk1 = hy0 ^ hz1;
    uint32_t hjk2 = hy1 ^ hz0;
    uint32_t hjk3 = hy1 ^ hz1;

    const float2* __restrict__ tab2 =
        reinterpret_cast<const float2*>(tables) + ((size_t)l << LOG2_T);
    const float4* __restrict__ tab4 =
        reinterpret_cast<const float4*>(tables) + ((size_t)l << (LOG2_T - 1));

    uint32_t i00 = (bx ^ hjk0) & TMASK;
    uint32_t i01 = (bx ^ hjk1) & TMASK;
    uint32_t i02 = (bx ^ hjk2) & TMASK;
    uint32_t i03 = (bx ^ hjk3) & TMASK;

    // 4 pair loads, front-batched (each = 16B aligned, one 32B sector)
    const float4 P0 = __ldg(&tab4[i00 >> 1]);
    const float4 P1v = __ldg(&tab4[i01 >> 1]);
    const float4 P2v = __ldg(&tab4[i02 >> 1]);
    const float4 P3v = __ldg(&tab4[i03 >> 1]);

    // odd bx -> x1 corners live elsewhere; load them (predicated per lane)
    const bool odd = (bx & 1u) != 0u;
    float2 X0 = make_float2(0.f, 0.f), X1 = X0, X2 = X0, X3 = X0;
    if (odd) {
        const uint32_t b1 = bx + 1u;
        X0 = __ldg(&tab2[(b1 ^ hjk0) & TMASK]);
        X1 = __ldg(&tab2[(b1 ^ hjk1) & TMASK]);
        X2 = __ldg(&tab2[(b1 ^ hjk2) & TMASK]);
        X3 = __ldg(&tab2[(b1 ^ hjk3) & TMASK]);
    }

    // unpack: pair = {entry 2m, entry 2m+1}; i0 odd -> corner0 is hi half
    float2 lo0 = make_float2(P0.x, P0.y),  hi0 = make_float2(P0.z, P0.w);
    float2 lo1 = make_float2(P1v.x, P1v.y), hi1 = make_float2(P1v.z, P1v.w);
    float2 lo2 = make_float2(P2v.x, P2v.y), hi2 = make_float2(P2v.z, P2v.w);
    float2 lo3 = make_float2(P3v.x, P3v.y), hi3 = make_float2(P3v.z, P3v.w);

    const bool s0 = (i00 & 1u), s1 = (i01 & 1u), s2 = (i02 & 1u), s3 = (i03 & 1u);

    const float2 e000 = s0 ? hi0 : lo0;
    const float2 e001 = s1 ? hi1 : lo1;
    const float2 e010 = s2 ? hi2 : lo2;
    const float2 e011 = s3 ? hi3 : lo3;
    // even bx: x1 corner is the other half of the pair
    const float2 e100 = odd ? X0 : (s0 ? lo0 : hi0);
    const float2 e101 = odd ? X1 : (s1 ? lo1 : hi1);
    const float2 e110 = odd ? X2 : (s2 ? lo2 : hi2);
    const float2 e111 = odd ? X3 : (s3 ? lo3 : hi3);

    // trilinear: collapse x, then y, then z (matches reference order)
    const float2 a00 = lerp2(e000, e100, wx);
    const float2 a01 = lerp2(e001, e101, wx);
    const float2 a10 = lerp2(e010, e110, wx);
    const float2 a11 = lerp2(e011, e111, wx);
    const float2 b0  = lerp2(a00, a10, wy);
    const float2 b1  = lerp2(a01, a11, wy);
    const float2 r   = lerp2(b0, b1, wz);

    // coalesced: warp covers 2 points x 16 levels -> 256B contiguous
    float2* __restrict__ o = reinterpret_cast<float2*>(out) + ((size_t)p << 4) + l;
    *o = r;
}

extern "C" void kernel_launch(void* const* d_in, const int* in_sizes, int n_in,
                              void* d_out, int out_size) {
    const float* x      = (const float*)d_in[0];
    const float* tables = (const float*)d_in[1];
    float* out          = (float*)d_out;

    const int n = in_sizes[0] / 3;
    const int blocks = (n + PPB - 1) / PPB;
    hashgrid_kernel<<<blocks, TPB>>>(x, tables, out, n);
}